// round 1
// baseline (speedup 1.0000x reference)
#include <cuda_runtime.h>

// SDF_75806172774865
// points: (N,P,3) f32 ; v,vn: (N,P,K,3) f32 ; sr: (N,P,K) f32 ; out: (N,) f32
// out[n] = sum_p sdf(n,p)^2, sdf = sum_k phi*dot / sum_k phi
// phi = inside ? ((1-d2/sr)^2)^2 : 1e-18, d2 = |p - v|^2, dot = vn . (p - v)

#define WARPS_PER_BLOCK 8
#define THREADS_PER_BLOCK (WARPS_PER_BLOCK * 32)

__global__ void sdf_zero_kernel(float* __restrict__ out, int n) {
    int i = blockIdx.x * blockDim.x + threadIdx.x;
    if (i < n) out[i] = 0.0f;
}

__global__ __launch_bounds__(THREADS_PER_BLOCK, 8)
void sdf_kernel(const float* __restrict__ points,
                const float* __restrict__ v,
                const float* __restrict__ vn,
                const float* __restrict__ sr,
                float* __restrict__ out,
                long long total_points, int P, int K) {
    const int warp = threadIdx.x >> 5;
    const int lane = threadIdx.x & 31;
    const long long gp = (long long)blockIdx.x * WARPS_PER_BLOCK + warp;

    __shared__ float s_part[WARPS_PER_BLOCK];

    float sdf2 = 0.0f;
    if (gp < total_points) {
        const float px = points[gp * 3 + 0];
        const float py = points[gp * 3 + 1];
        const float pz = points[gp * 3 + 2];

        const float* __restrict__ vrow  = v  + gp * (long long)K * 3;
        const float* __restrict__ vnrow = vn + gp * (long long)K * 3;
        const float* __restrict__ srow  = sr + gp * (long long)K;

        float num = 0.0f, den = 0.0f;
        for (int k = lane; k < K; k += 32) {
            const float vx = vrow[3 * k + 0];
            const float vy = vrow[3 * k + 1];
            const float vz = vrow[3 * k + 2];
            const float nx = vnrow[3 * k + 0];
            const float ny = vnrow[3 * k + 1];
            const float nz = vnrow[3 * k + 2];
            const float s  = srow[k];

            const float dx = px - vx;
            const float dy = py - vy;
            const float dz = pz - vz;
            const float d2 = fmaf(dx, dx, fmaf(dy, dy, dz * dz));

            const float w  = 1.0f - d2 * __frcp_rn(s);
            const float w2 = w * w;
            const float phi = (d2 < s) ? (w2 * w2) : 1e-18f;

            const float dot = fmaf(nx, dx, fmaf(ny, dy, nz * dz));
            num = fmaf(phi, dot, num);
            den += phi;
        }
        // warp reduce (num, den)
        #pragma unroll
        for (int o = 16; o > 0; o >>= 1) {
            num += __shfl_xor_sync(0xffffffffu, num, o);
            den += __shfl_xor_sync(0xffffffffu, den, o);
        }
        const float sdf = num / den;
        sdf2 = sdf * sdf;
    }

    if (lane == 0) s_part[warp] = (gp < total_points) ? sdf2 : 0.0f;
    __syncthreads();

    if (threadIdx.x == 0) {
        // Block covers 8 consecutive points; n is nondecreasing across them.
        const long long gp0 = (long long)blockIdx.x * WARPS_PER_BLOCK;
        const int n0 = (int)(gp0 / P);
        float sum0 = 0.0f;
        #pragma unroll
        for (int i = 0; i < WARPS_PER_BLOCK; i++) {
            const long long gpi = gp0 + i;
            if (gpi >= total_points) break;
            const int ni = (int)(gpi / P);
            if (ni == n0) sum0 += s_part[i];
            else          atomicAdd(&out[ni], s_part[i]);
        }
        atomicAdd(&out[n0], sum0);
    }
}

extern "C" void kernel_launch(void* const* d_in, const int* in_sizes, int n_in,
                              void* d_out, int out_size) {
    const float* points = (const float*)d_in[0];
    const float* v      = (const float*)d_in[1];
    const float* vn     = (const float*)d_in[2];
    const float* sr     = (const float*)d_in[3];
    float* out = (float*)d_out;

    const long long total_points = (long long)in_sizes[0] / 3;       // N*P
    const int N = out_size;                                           // (N,)
    const int P = (int)(total_points / N);
    const int K = (int)((long long)in_sizes[3] / total_points);       // sr = N*P*K

    sdf_zero_kernel<<<1, 32>>>(out, out_size);

    const long long nblocks = (total_points + WARPS_PER_BLOCK - 1) / WARPS_PER_BLOCK;
    sdf_kernel<<<(unsigned)nblocks, THREADS_PER_BLOCK>>>(
        points, v, vn, sr, out, total_points, P, K);
}

// round 2
// speedup vs baseline: 1.3440x; 1.3440x over previous
#include <cuda_runtime.h>

// SDF_75806172774865
// points: (N,P,3) f32 ; v,vn: (N,P,K,3) f32 ; sr: (N,P,K) f32 ; out: (N,) f32
// out[n] = sum_p sdf(n,p)^2, sdf = sum_k phi*dot / sum_k phi
// phi = inside ? ((1-d2/sr)^2)^2 : 1e-18, d2 = |p - v|^2, dot = vn . (p - v)
//
// R2: stage per-block slab (8 points x (v,vn,sr)) into smem via coalesced
// float4 loads; compute from smem (stride-3 -> conflict-free). Cuts global
// load issue slots ~4x and L1 wavefronts ~4x vs scalar LDG.32 path.

#define K_FIX 60
#define WARPS_PER_BLOCK 8
#define THREADS_PER_BLOCK (WARPS_PER_BLOCK * 32)
#define ROWF (K_FIX * 3)                      // 180 floats per point row (v / vn)
#define V_F4  (WARPS_PER_BLOCK * ROWF / 4)    // 360 float4 per block for v
#define SR_F4 (WARPS_PER_BLOCK * K_FIX / 4)   // 120 float4 per block for sr

__global__ void sdf_zero_kernel(float* __restrict__ out, int n) {
    int i = blockIdx.x * blockDim.x + threadIdx.x;
    if (i < n) out[i] = 0.0f;
}

__global__ __launch_bounds__(THREADS_PER_BLOCK, 8)
void sdf_kernel(const float* __restrict__ points,
                const float* __restrict__ v,
                const float* __restrict__ vn,
                const float* __restrict__ sr,
                float* __restrict__ out,
                long long total_points, int P) {
    __shared__ float s_v [WARPS_PER_BLOCK * ROWF];
    __shared__ float s_vn[WARPS_PER_BLOCK * ROWF];
    __shared__ float s_sr[WARPS_PER_BLOCK * K_FIX];
    __shared__ float s_part[WARPS_PER_BLOCK];

    const int tid  = threadIdx.x;
    const int warp = tid >> 5;
    const int lane = tid & 31;
    const long long gp0 = (long long)blockIdx.x * WARPS_PER_BLOCK;
    const long long gp  = gp0 + warp;

    // How many points this block actually owns (tail-safe)
    const int npts = (int)min((long long)WARPS_PER_BLOCK, total_points - gp0);

    // ---- Stage slab into smem with float4 loads (fully coalesced) ----
    {
        const float4* __restrict__ gv  = (const float4*)(v  + gp0 * ROWF);
        const float4* __restrict__ gvn = (const float4*)(vn + gp0 * ROWF);
        const float4* __restrict__ gsr = (const float4*)(sr + gp0 * K_FIX);
        float4* sv  = (float4*)s_v;
        float4* svn = (float4*)s_vn;
        float4* ssr = (float4*)s_sr;

        const int nv4  = npts * (ROWF / 4);
        const int nsr4 = npts * (K_FIX / 4);
        #pragma unroll
        for (int i = tid; i < V_F4; i += THREADS_PER_BLOCK)
            if (i < nv4) sv[i] = gv[i];
        #pragma unroll
        for (int i = tid; i < V_F4; i += THREADS_PER_BLOCK)
            if (i < nv4) svn[i] = gvn[i];
        if (tid < SR_F4 && tid < nsr4) ssr[tid] = gsr[tid];
    }
    __syncthreads();

    // ---- Compute: one warp per point, k strided by lane ----
    float sdf2 = 0.0f;
    if (gp < total_points) {
        const float px = points[gp * 3 + 0];
        const float py = points[gp * 3 + 1];
        const float pz = points[gp * 3 + 2];

        const float* __restrict__ vrow  = s_v  + warp * ROWF;
        const float* __restrict__ vnrow = s_vn + warp * ROWF;
        const float* __restrict__ srow  = s_sr + warp * K_FIX;

        float num = 0.0f, den = 0.0f;
        #pragma unroll
        for (int kk = 0; kk < 2; kk++) {
            const int k = lane + kk * 32;
            if (k < K_FIX) {
                const float vx = vrow[3 * k + 0];
                const float vy = vrow[3 * k + 1];
                const float vz = vrow[3 * k + 2];
                const float nx = vnrow[3 * k + 0];
                const float ny = vnrow[3 * k + 1];
                const float nz = vnrow[3 * k + 2];
                const float s  = srow[k];

                const float dx = px - vx;
                const float dy = py - vy;
                const float dz = pz - vz;
                const float d2 = fmaf(dx, dx, fmaf(dy, dy, dz * dz));

                const float w   = 1.0f - d2 * __frcp_rn(s);
                const float w2  = w * w;
                const float phi = (d2 < s) ? (w2 * w2) : 1e-18f;

                const float dot = fmaf(nx, dx, fmaf(ny, dy, nz * dz));
                num = fmaf(phi, dot, num);
                den += phi;
            }
        }
        #pragma unroll
        for (int o = 16; o > 0; o >>= 1) {
            num += __shfl_xor_sync(0xffffffffu, num, o);
            den += __shfl_xor_sync(0xffffffffu, den, o);
        }
        const float sdf = num / den;
        sdf2 = sdf * sdf;
    }

    if (lane == 0) s_part[warp] = (gp < total_points) ? sdf2 : 0.0f;
    __syncthreads();

    if (tid == 0) {
        const int n0 = (int)(gp0 / P);
        float sum0 = 0.0f;
        #pragma unroll
        for (int i = 0; i < WARPS_PER_BLOCK; i++) {
            const long long gpi = gp0 + i;
            if (gpi >= total_points) break;
            const int ni = (int)(gpi / P);
            if (ni == n0) sum0 += s_part[i];
            else          atomicAdd(&out[ni], s_part[i]);
        }
        atomicAdd(&out[n0], sum0);
    }
}

extern "C" void kernel_launch(void* const* d_in, const int* in_sizes, int n_in,
                              void* d_out, int out_size) {
    const float* points = (const float*)d_in[0];
    const float* v      = (const float*)d_in[1];
    const float* vn     = (const float*)d_in[2];
    const float* sr     = (const float*)d_in[3];
    float* out = (float*)d_out;

    const long long total_points = (long long)in_sizes[0] / 3;  // N*P
    const int N = out_size;
    const int P = (int)(total_points / N);

    sdf_zero_kernel<<<1, 32>>>(out, out_size);

    const long long nblocks = (total_points + WARPS_PER_BLOCK - 1) / WARPS_PER_BLOCK;
    sdf_kernel<<<(unsigned)nblocks, THREADS_PER_BLOCK>>>(
        points, v, vn, sr, out, total_points, P);
}

// round 3
// speedup vs baseline: 1.7304x; 1.2875x over previous
#include <cuda_runtime.h>
#include <cstdint>

// SDF_75806172774865 — R3: persistent blocks, double-buffered cp.async pipeline.
// points: (N,P,3) f32 ; v,vn: (N,P,K,3) f32 ; sr: (N,P,K) f32 ; out: (N,) f32

#define K_FIX 60
#define SLAB 8                         // points per slab (one warp per point)
#define THREADS_PER_BLOCK 256
#define ROWF (K_FIX * 3)               // 180 floats per point row
#define V4_SLAB (SLAB * ROWF / 4)      // 360 float4 (v), same for vn
#define SR4_SLAB (SLAB * K_FIX / 4)    // 120 float4
#define PT4_SLAB (SLAB * 3 / 4)        // 6 float4
#define BUF_FLOATS (SLAB*ROWF*2 + SLAB*K_FIX + SLAB*3)  // 3384 floats = 13536 B
#define NMAX 8

__device__ __forceinline__ void cp_async16(void* smem_ptr, const void* gptr) {
    uint32_t sa = (uint32_t)__cvta_generic_to_shared(smem_ptr);
    asm volatile("cp.async.cg.shared.global [%0], [%1], 16;" :: "r"(sa), "l"(gptr));
}
#define CP_COMMIT() asm volatile("cp.async.commit_group;")
#define CP_WAIT1()  asm volatile("cp.async.wait_group 1;")
#define CP_WAIT0()  asm volatile("cp.async.wait_group 0;")

__global__ void sdf_zero_kernel(float* __restrict__ out, int n) {
    int i = blockIdx.x * blockDim.x + threadIdx.x;
    if (i < n) out[i] = 0.0f;
}

__device__ __forceinline__ void stage_slab(
    float* __restrict__ buf,
    const float* __restrict__ v, const float* __restrict__ vn,
    const float* __restrict__ sr, const float* __restrict__ points,
    long long slab, int tid, long long total_points)
{
    const long long gp0 = slab * SLAB;
    const int npts = (int)min((long long)SLAB, total_points - gp0);
    const float4* gv  = (const float4*)(v      + gp0 * ROWF);
    const float4* gvn = (const float4*)(vn     + gp0 * ROWF);
    const float4* gsr = (const float4*)(sr     + gp0 * K_FIX);
    const float4* gpt = (const float4*)(points + gp0 * 3);
    float4* sv  = (float4*)buf;
    float4* svn = sv  + V4_SLAB;
    float4* ssr = svn + V4_SLAB;
    float4* spt = ssr + SR4_SLAB;

    const int nv4  = npts * (ROWF / 4);
    const int nsr4 = npts * (K_FIX / 4);
    const int npt4 = (npts * 3 + 3) / 4;

    int i = tid;
    #pragma unroll
    for (int it = 0; it < 4; it++, i += THREADS_PER_BLOCK) {
        if (i < V4_SLAB) {
            if (i < nv4) cp_async16(sv + i, gv + i);
        } else if (i < 2 * V4_SLAB) {
            int j = i - V4_SLAB;
            if (j < nv4) cp_async16(svn + j, gvn + j);
        } else if (i < 2 * V4_SLAB + SR4_SLAB) {
            int j = i - 2 * V4_SLAB;
            if (j < nsr4) cp_async16(ssr + j, gsr + j);
        } else if (i < 2 * V4_SLAB + SR4_SLAB + PT4_SLAB) {
            int j = i - (2 * V4_SLAB + SR4_SLAB);
            if (j < npt4) cp_async16(spt + j, gpt + j);
        }
    }
}

__global__ __launch_bounds__(THREADS_PER_BLOCK)
void sdf_kernel(const float* __restrict__ points,
                const float* __restrict__ v,
                const float* __restrict__ vn,
                const float* __restrict__ sr,
                float* __restrict__ out,
                long long total_points, int P, int N,
                long long total_slabs, long long slabs_per_block) {
    __shared__ __align__(16) float s_buf[2][BUF_FLOATS];
    __shared__ float s_acc[SLAB * NMAX];

    const int tid  = threadIdx.x;
    const int warp = tid >> 5;
    const int lane = tid & 31;

    const long long s0 = (long long)blockIdx.x * slabs_per_block;
    const long long s1 = min(s0 + slabs_per_block, total_slabs);
    if (s0 >= s1) return;

    if (tid < SLAB * NMAX) s_acc[tid] = 0.0f;

    // Prologue: stage first slab
    stage_slab(s_buf[s0 & 1], v, vn, sr, points, s0, tid, total_points);
    CP_COMMIT();

    for (long long s = s0; s < s1; s++) {
        const int cur = (int)(s & 1);
        __syncthreads();   // compute(s-1) done before overwriting buf[cur^1]
        if (s + 1 < s1) {
            stage_slab(s_buf[cur ^ 1], v, vn, sr, points, s + 1, tid, total_points);
            CP_COMMIT();
            CP_WAIT1();    // slab s resident
        } else {
            CP_WAIT0();
        }
        __syncthreads();

        const float* __restrict__ buf = s_buf[cur];
        const long long gp = s * SLAB + warp;
        if (gp < total_points) {
            const float* __restrict__ vrow  = buf + warp * ROWF;
            const float* __restrict__ vnrow = buf + SLAB * ROWF + warp * ROWF;
            const float* __restrict__ srow  = buf + 2 * SLAB * ROWF + warp * K_FIX;
            const float* __restrict__ prow  = buf + 2 * SLAB * ROWF + SLAB * K_FIX + warp * 3;
            const float px = prow[0], py = prow[1], pz = prow[2];

            float num = 0.0f, den = 0.0f;
            #pragma unroll
            for (int kk = 0; kk < 2; kk++) {
                const int k = lane + kk * 32;
                if (k < K_FIX) {
                    const float vx = vrow[3 * k + 0];
                    const float vy = vrow[3 * k + 1];
                    const float vz = vrow[3 * k + 2];
                    const float nx = vnrow[3 * k + 0];
                    const float ny = vnrow[3 * k + 1];
                    const float nz = vnrow[3 * k + 2];
                    const float sv = srow[k];

                    const float dx = px - vx;
                    const float dy = py - vy;
                    const float dz = pz - vz;
                    const float d2 = fmaf(dx, dx, fmaf(dy, dy, dz * dz));

                    const float w   = 1.0f - d2 * __frcp_rn(sv);
                    const float w2  = w * w;
                    const float phi = (d2 < sv) ? (w2 * w2) : 1e-18f;

                    const float dot = fmaf(nx, dx, fmaf(ny, dy, nz * dz));
                    num = fmaf(phi, dot, num);
                    den += phi;
                }
            }
            #pragma unroll
            for (int o = 16; o > 0; o >>= 1) {
                num += __shfl_xor_sync(0xffffffffu, num, o);
                den += __shfl_xor_sync(0xffffffffu, den, o);
            }
            if (lane == 0) {
                const float sdf  = num / den;
                const float sdf2 = sdf * sdf;
                const int ni = (int)(gp / P);
                if (ni < NMAX) s_acc[warp * NMAX + ni] += sdf2;  // warp-private slot
                else           atomicAdd(&out[ni], sdf2);
            }
        }
    }

    __syncthreads();
    if (tid < N && tid < NMAX) {
        float sum = 0.0f;
        #pragma unroll
        for (int w = 0; w < SLAB; w++) sum += s_acc[w * NMAX + tid];
        atomicAdd(&out[tid], sum);
    }
}

extern "C" void kernel_launch(void* const* d_in, const int* in_sizes, int n_in,
                              void* d_out, int out_size) {
    const float* points = (const float*)d_in[0];
    const float* v      = (const float*)d_in[1];
    const float* vn     = (const float*)d_in[2];
    const float* sr     = (const float*)d_in[3];
    float* out = (float*)d_out;

    const long long total_points = (long long)in_sizes[0] / 3;  // N*P
    const int N = out_size;
    const int P = (int)(total_points / N);

    sdf_zero_kernel<<<1, 32>>>(out, out_size);

    const long long total_slabs = (total_points + SLAB - 1) / SLAB;
    const long long max_blocks  = 148LL * 8;
    const long long grid        = min(total_slabs, max_blocks);
    const long long spb         = (total_slabs + grid - 1) / grid;

    sdf_kernel<<<(unsigned)grid, THREADS_PER_BLOCK>>>(
        points, v, vn, sr, out, total_points, P, N, total_slabs, spb);
}